// round 12
// baseline (speedup 1.0000x reference)
#include <cuda_runtime.h>
#include <math.h>
#include <limits.h>

#define NIMG 4
#define NPRI 3106
#define NCLS 20      // classes 1..20 (background excluded)
#define NTOT 21
#define NPAD 4096    // max pow2 bound for sort array
#define TOPK 200

#define MIN_SCORE 0.05f
#define MAX_OVERLAP 0.45f

#define NMS_NT 1024
#define NWARPS (NMS_NT / 32)   // 32

#define CHUNK 128
#define CW 4                 // CHUNK/32 mask words

// ---------------- device scratch (no allocations allowed) ----------------
__device__ float  g_cls[NIMG][NCLS][NPRI];      // class-major probs
__device__ float4 g_box[NIMG][NPRI];            // decoded boxes x1,y1,x2,y2
__device__ float  g_candScore[NIMG][NCLS][TOPK];
__device__ float4 g_candBox[NIMG][NCLS][TOPK];
__device__ int    g_candCnt[NIMG][NCLS];

// Fast double-precision exp (Cody-Waite + deg-12 Taylor, rel err ~2^-52).
__device__ __forceinline__ float exp_df(float xf)
{
    double x = (double)xf;
    float nf = rintf(xf * 1.4426950408889634f);
    double n = (double)nf;
    double r = fma(n, -0.6931471805599453, x);
    r = fma(n, -2.3190468138462996e-17, r);
    double p = 2.08767569878681e-09;
    p = fma(p, r, 2.505210838544172e-08);
    p = fma(p, r, 2.755731922398589e-07);
    p = fma(p, r, 2.755731922398589e-06);
    p = fma(p, r, 2.480158730158730e-05);
    p = fma(p, r, 1.984126984126984e-04);
    p = fma(p, r, 1.388888888888889e-03);
    p = fma(p, r, 8.333333333333333e-03);
    p = fma(p, r, 4.166666666666666e-02);
    p = fma(p, r, 1.666666666666667e-01);
    p = fma(p, r, 0.5);
    p = fma(p, r, 1.0);
    p = fma(p, r, 1.0);
    long long ni = (long long)nf;
    double sc = __longlong_as_double((ni + 1023LL) << 52);
    return (float)(p * sc);
}

// ---------------- kernel 1: softmax + box decode (2 threads per row) ----------
__global__ void softmax_decode_kernel(const float* __restrict__ locs,
                                      const float* __restrict__ scores,
                                      const float* __restrict__ priors)
{
    int gid  = blockIdx.x * blockDim.x + threadIdx.x;
    int row  = gid >> 1;
    int half = gid & 1;
    bool real = (row < NIMG * NPRI);
    if (!real) row = NIMG * NPRI - 1;          // clamp; keep lanes alive for shfl
    int img = row / NPRI;
    int p   = row - img * NPRI;

    const float* s  = scores + (size_t)row * NTOT;
    const float* l  = locs   + (size_t)row * 4;
    const float* pr = priors + (size_t)p * 4;

    // half0: classes 0..10 (11), half1: classes 11..20 (10)
    int c0 = half ? 11 : 0;
    int cn = half ? 10 : 11;

    float zv[11];
    float m = -INFINITY;
    #pragma unroll
    for (int k = 0; k < 11; k++) {
        if (k < cn) { zv[k] = s[c0 + k]; m = fmaxf(m, zv[k]); }
    }
    m = fmaxf(m, __shfl_xor_sync(0xffffffffu, m, 1));

    float e[11];
    double dsum = 0.0;
    #pragma unroll
    for (int k = 0; k < 11; k++) {
        if (k < cn) { e[k] = exp_df(zv[k] - m); dsum += (double)e[k]; }
    }
    // decode exp in parallel: half0 -> w, half1 -> h
    float dexp = half ? (exp_df(__fdiv_rn(l[3], 5.0f)) * pr[3])
                      : (exp_df(__fdiv_rn(l[2], 5.0f)) * pr[2]);

    dsum += __shfl_xor_sync(0xffffffffu, dsum, 1);
    float fsum = (float)dsum;

    if (real) {
        if (half == 0) {
            #pragma unroll
            for (int k = 1; k < 11; k++)          // skip background class 0
                g_cls[img][k - 1][p] = __fdiv_rn(e[k], fsum);
        } else {
            #pragma unroll
            for (int k = 0; k < 10; k++)
                g_cls[img][10 + k][p] = __fdiv_rn(e[k], fsum);
        }
    }

    float other = __shfl_xor_sync(0xffffffffu, dexp, 1);
    if (real && half == 0) {
        float w = dexp, h = other;
        float cx = __fdiv_rn(l[0] * pr[2], 10.0f) + pr[0];
        float cy = __fdiv_rn(l[1] * pr[3], 10.0f) + pr[1];
        float4 b;
        b.x = cx - __fdiv_rn(w, 2.0f);
        b.y = cy - __fdiv_rn(h, 2.0f);
        b.z = cx + __fdiv_rn(w, 2.0f);
        b.w = cy + __fdiv_rn(h, 2.0f);
        g_box[img][p] = b;
    }
}

// overlap test with precomputed areas; bit-identical to reference iou > T
__device__ __forceinline__ bool overlap_f(float4 a, float aA, float4 b, float aB)
{
    float dx = fminf(a.z, b.z) - fmaxf(a.x, b.x);
    float dy = fminf(a.w, b.w) - fmaxf(a.y, b.y);
    if (dx > 0.0f && dy > 0.0f) {
        float inter = dx * dy;
        return __fdiv_rn(inter, aA + aB - inter) > MAX_OVERLAP;
    }
    return false;   // inter==0 -> iou==0 <= T
}

// exclusive warp-count prefix via shfl scan; s_wcnt[lane] valid for lane<32.
__device__ __forceinline__ void scan_counts(const int* s_wcnt, int wid, int lane,
                                            int& wpre, int& wsum)
{
    int x = s_wcnt[lane];
    #pragma unroll
    for (int d = 1; d < 32; d <<= 1) {
        int v = __shfl_up_sync(0xffffffffu, x, d);
        if (lane >= d) x += v;
    }
    wsum = __shfl_sync(0xffffffffu, x, 31);
    wpre = (wid == 0) ? 0 : __shfl_sync(0xffffffffu, x, wid - 1);
}

// ---------------- kernel 2: per-(image,class) greedy NMS ----------------
// Dynamic shared layout:
//   [0,      32768)   u64    skey64[NPAD]      (score_bits<<32 | ~idx)
//   [32768,  82464)   float4 sbox[NPRI]
//   [82464,  94888)   float  sscore[NPRI]
//   [94888, 107312)   float  sarea[NPRI]
#define SMEM_NMS_BYTES 107392

__global__ void __launch_bounds__(NMS_NT, 1)
nms_kernel()
{
    extern __shared__ char sm[];
    unsigned long long* skey64 = (unsigned long long*)(sm);
    float4*             sbox   = (float4*)(sm + 32768);
    float*              sscore = (float*)(sm + 82464);
    float*              sarea  = (float*)(sm + 94888);
    __shared__ int      s_wcnt[NWARPS];
    __shared__ unsigned s_omask[CHUNK * CW];   // in-chunk column masks
    __shared__ unsigned s_keptw[CW];
    __shared__ int      s_nk;
    __shared__ float4   s_kbox[CHUNK];
    __shared__ float    s_karea[CHUNK];

    int img  = blockIdx.x / NCLS;
    int c    = blockIdx.x % NCLS;
    int tid  = threadIdx.x;
    int wid  = tid >> 5;
    int lane = tid & 31;
    unsigned lmask = (1u << lane) - 1u;

    // ---- Phase A: stable compaction of valid entries ----
    int base = 0;
    for (int bp = 0; bp < NPRI; bp += NMS_NT) {
        int p = bp + tid;
        float sc = (p < NPRI) ? g_cls[img][c][p] : 0.0f;
        bool ok = (p < NPRI) && (sc > MIN_SCORE);
        unsigned b = __ballot_sync(0xffffffffu, ok);
        if (lane == 0) s_wcnt[wid] = __popc(b);
        __syncthreads();
        int wpre, wsum;
        scan_counts(s_wcnt, wid, lane, wpre, wsum);
        int rank = base + wpre + __popc(b & lmask);
        if (ok)
            skey64[rank] = ((unsigned long long)__float_as_uint(sc) << 32)
                         | (unsigned int)(~p);
        base += wsum;
        __syncthreads();
    }
    int nvalid = base;

    int keptTotal = 0;

    if (nvalid > 0) {
        int npow = 32;
        while (npow < nvalid) npow <<= 1;
        for (int t = nvalid + tid; t < npow; t += NMS_NT)
            skey64[t] = 0ull;
        __syncthreads();

        // ---- Phase B: bitonic sort, descending u64 (score desc, idx asc) ----
        for (int k = 2; k <= npow; k <<= 1) {
            for (int j = k >> 1; j > 0; j >>= 1) {
                for (int t = tid; t < npow; t += NMS_NT) {
                    int l = t ^ j;
                    if (l > t) {
                        unsigned long long ka = skey64[t], kb = skey64[l];
                        bool asc = ((t & k) == 0);
                        if ((kb > ka) == asc) {
                            skey64[t] = kb;
                            skey64[l] = ka;
                        }
                    }
                }
                __syncthreads();
            }
        }

        // ---- Phase C: gather boxes + scores + areas ----
        for (int i = tid; i < nvalid; i += NMS_NT) {
            unsigned long long key = skey64[i];
            unsigned idx = ~((unsigned)key);
            float4 b = g_box[img][idx];
            sbox[i]   = b;
            sscore[i] = __uint_as_float((unsigned)(key >> 32));
            sarea[i]  = (b.z - b.x) * (b.w - b.y);
        }
        __syncthreads();

        // ---- Phase D: 128-wide chunked greedy ----
        int nrem = nvalid;
        while (nrem > 0 && keptTotal < TOPK) {
            int m  = min(CHUNK, nrem);
            int mw = (m + 31) >> 5;

            // 1) in-chunk COLUMN masks: s_omask[j][w] = bits i (i<j, word w)
            //    overlapping j. thread = (column j = tid>>3, segment h = tid&7),
            //    16 candidate tests each, shfl-merged into 32-bit words.
            {
                int j = tid >> 3, h = tid & 7;
                unsigned bits16 = 0;
                if (j < m) {
                    float4 bj = sbox[j];
                    float  aj = sarea[j];
                    int i0 = h << 4;
                    int hi = min(16, j - i0);
                    for (int b = 0; b < hi; b++) {
                        if (overlap_f(sbox[i0 + b], sarea[i0 + b], bj, aj))
                            bits16 |= 1u << b;
                    }
                }
                unsigned other = __shfl_xor_sync(0xffffffffu, bits16, 1);
                if (j < m && (h & 1) == 0)
                    s_omask[j * CW + (h >> 1)] = bits16 | (other << 16);
            }
            __syncthreads();

            // 2) warp 0: ballot resolve over mw groups of 32 (no IoU)
            if (wid == 0) {
                unsigned keptw[CW];
                #pragma unroll
                for (int w = 0; w < CW; w++) keptw[w] = 0u;
                int gbase = 0;
                for (int g = 0; g < mw; g++) {
                    int idx = (g << 5) + lane;
                    bool valid = idx < m;
                    bool supp = false;
                    unsigned over_g = 0;
                    if (valid) {
                        for (int w = 0; w < g; w++)
                            if (s_omask[idx * CW + w] & keptw[w]) supp = true;
                        over_g = s_omask[idx * CW + g];  // bits < lane only
                    }
                    unsigned unres = __ballot_sync(0xffffffffu, valid && !supp);
                    unsigned kept = 0;
                    while (unres) {
                        int i = __ffs(unres) - 1;
                        kept |= 1u << i;
                        unsigned ri = __ballot_sync(0xffffffffu,
                                                    (over_g >> i) & 1u);
                        unres &= ~(ri | (1u << i));
                    }
                    keptw[g] = kept;
                    gbase += __popc(kept);
                }
                if (lane < CW) s_keptw[lane] = keptw[lane];
                if (lane == 0) s_nk = gbase;
            }
            __syncthreads();

            int nk = s_nk;

            // 3) export kept to global + densify kept boxes (parallel)
            if (tid < m) {
                int w = tid >> 5;
                unsigned km = s_keptw[w];
                if ((km >> lane) & 1u) {
                    int rank = __popc(km & lmask);
                    for (int ww = 0; ww < w; ww++)
                        rank += __popc(s_keptw[ww]);
                    int slot = keptTotal + rank;
                    if (slot < TOPK) {
                        g_candScore[img][c][slot] = sscore[tid];
                        g_candBox[img][c][slot]   = sbox[tid];
                    }
                    s_kbox[rank]  = sbox[tid];
                    s_karea[rank] = sarea[tid];
                }
            }
            keptTotal += nk;
            if (keptTotal >= TOPK) break;
            if (nrem <= m) { nrem = 0; break; }
            __syncthreads();   // s_kbox ready; guards sbox overwrites below

            // 4) fused suppress (vs nk kept, early-exit) + stable compact
            int newbase = 0;
            for (int start = m; start < nrem; start += NMS_NT) {
                int j = start + tid;
                bool ok = (j < nrem);
                float key = 0.0f, ar = 0.0f; float4 bx;
                if (ok) {
                    key = sscore[j]; bx = sbox[j]; ar = sarea[j];
                    for (int t = 0; t < nk; t++) {
                        if (overlap_f(s_kbox[t], s_karea[t], bx, ar)) {
                            ok = false; break;
                        }
                    }
                }
                unsigned b = __ballot_sync(0xffffffffu, ok);
                if (lane == 0) s_wcnt[wid] = __popc(b);
                __syncthreads();          // reads done; safe to write
                int wpre, wsum;
                scan_counts(s_wcnt, wid, lane, wpre, wsum);
                int rank = newbase + wpre + __popc(b & lmask);
                if (ok) { sscore[rank] = key; sbox[rank] = bx; sarea[rank] = ar; }
                newbase += wsum;
                __syncthreads();
            }
            nrem = newbase;
        }
    }

    // pad unused candidate slots; publish kept count
    int kc = min(keptTotal, TOPK);
    for (int r = kc + tid; r < TOPK; r += NMS_NT)
        g_candScore[img][c][r] = -INFINITY;
    if (tid == 0) g_candCnt[img][c] = keptTotal;
}

// ---------------- kernel 3: per-image 20-way sorted merge top-200 ----------------
#define TKM_NT 256
__global__ void __launch_bounds__(TKM_NT, 1)
topk_merge_kernel(float* __restrict__ out)
{
    __shared__ float ssc[NCLS * TOPK];
    __shared__ float osc[TOPK];
    __shared__ int   ocls[TOPK];
    __shared__ int   orow[TOPK];
    __shared__ int   s_total, s_found;

    int img = blockIdx.x;
    int tid = threadIdx.x;

    const float* src = &g_candScore[img][0][0];
    for (int t = tid; t < NCLS * TOPK; t += TKM_NT)
        ssc[t] = src[t];
    if (tid == 0) {
        int tt = 0;
        for (int c = 0; c < NCLS; c++) tt += g_candCnt[img][c];
        s_total = tt;
        s_found = 0;
    }
    __syncthreads();

    if (tid < 32) {
        int lane = tid;
        int r = 0;
        float h = (lane < NCLS) ? ssc[lane * TOPK] : -INFINITY;
        int found = 0;
        for (int k = 0; k < TOPK; k++) {
            unsigned key = (h == -INFINITY) ? 0u
                         : (__float_as_uint(h) | 0x80000000u);
            unsigned mx = __reduce_max_sync(0xffffffffu, key);
            if (mx == 0u) break;
            unsigned tie = __ballot_sync(0xffffffffu, key == mx);
            int cwin = __ffs(tie) - 1;           // smallest class wins tie
            if (lane == cwin) {
                osc[k]  = h;
                ocls[k] = cwin;
                orow[k] = r;
                r++;
                h = (r < TOPK) ? ssc[cwin * TOPK + r] : -INFINITY;
            }
            found = k + 1;
        }
        if (lane == 0) s_found = found;
    }
    __syncthreads();

    float* outBoxes  = out;                                     // [4,200,4]
    float* outLabels = out + NIMG * TOPK * 4;                   // [4,200]
    float* outScores = out + NIMG * TOPK * 4 + NIMG * TOPK;     // [4,200]
    float* outCount  = out + NIMG * TOPK * 4 + 2 * NIMG * TOPK; // [4]

    int found = s_found;
    for (int k = tid; k < TOPK; k += TKM_NT) {
        bool has = (k < found);
        float4 b = make_float4(0.f, 0.f, 0.f, 0.f);
        int lab = 0;
        float sc = 0.f;
        if (has) {
            b   = g_candBox[img][ocls[k]][orow[k]];
            lab = ocls[k] + 1;
            sc  = osc[k];
        }
        int basei = (img * TOPK + k) * 4;
        outBoxes[basei + 0] = b.x;
        outBoxes[basei + 1] = b.y;
        outBoxes[basei + 2] = b.z;
        outBoxes[basei + 3] = b.w;
        outLabels[img * TOPK + k] = (float)lab;
        outScores[img * TOPK + k] = sc;
    }
    __syncthreads();

    if (tid == 0) {
        int cnt = min(s_total, TOPK);
        if (cnt == 0) {
            int basei = img * TOPK * 4;
            outBoxes[basei + 0] = 0.0f;
            outBoxes[basei + 1] = 0.0f;
            outBoxes[basei + 2] = 1.0f;
            outBoxes[basei + 3] = 1.0f;
            cnt = 1;
        }
        outCount[img] = (float)cnt;
    }
}

// ---------------- launch ----------------
extern "C" void kernel_launch(void* const* d_in, const int* in_sizes, int n_in,
                              void* d_out, int out_size)
{
    const float* locs   = (const float*)d_in[0];  // (4,3106,4)
    const float* scores = (const float*)d_in[1];  // (4,3106,21)
    const float* priors = (const float*)d_in[2];  // (3106,4)
    float* out = (float*)d_out;

    static bool attr_set = false;
    if (!attr_set) {
        cudaFuncSetAttribute(nms_kernel,
                             cudaFuncAttributeMaxDynamicSharedMemorySize,
                             SMEM_NMS_BYTES);
        attr_set = true;
    }

    int threads2 = NIMG * NPRI * 2;               // 2 threads per row
    softmax_decode_kernel<<<(threads2 + 63) / 64, 64>>>(locs, scores, priors);
    nms_kernel<<<NIMG * NCLS, NMS_NT, SMEM_NMS_BYTES>>>();
    topk_merge_kernel<<<NIMG, TKM_NT>>>(out);
}

// round 13
// speedup vs baseline: 1.1532x; 1.1532x over previous
#include <cuda_runtime.h>
#include <math.h>
#include <limits.h>

#define NIMG 4
#define NPRI 3106
#define NCLS 20      // classes 1..20 (background excluded)
#define NTOT 21
#define NPAD 4096    // max pow2 bound for sort array
#define TOPK 200

#define MIN_SCORE 0.05f
#define MAX_OVERLAP 0.45f

#define NMS_NT 1024
#define NWARPS (NMS_NT / 32)   // 32

#define CHUNK 64

// ---------------- device scratch (no allocations allowed) ----------------
__device__ float  g_cls[NIMG][NCLS][NPRI];      // class-major probs
__device__ float4 g_box[NIMG][NPRI];            // decoded boxes x1,y1,x2,y2
__device__ float  g_candScore[NIMG][NCLS][TOPK];
__device__ float4 g_candBox[NIMG][NCLS][TOPK];
__device__ int    g_candCnt[NIMG][NCLS];

// Fast double-precision exp (Cody-Waite + deg-12 Taylor, rel err ~2^-52).
__device__ __forceinline__ float exp_df(float xf)
{
    double x = (double)xf;
    float nf = rintf(xf * 1.4426950408889634f);
    double n = (double)nf;
    double r = fma(n, -0.6931471805599453, x);
    r = fma(n, -2.3190468138462996e-17, r);
    double p = 2.08767569878681e-09;
    p = fma(p, r, 2.505210838544172e-08);
    p = fma(p, r, 2.755731922398589e-07);
    p = fma(p, r, 2.755731922398589e-06);
    p = fma(p, r, 2.480158730158730e-05);
    p = fma(p, r, 1.984126984126984e-04);
    p = fma(p, r, 1.388888888888889e-03);
    p = fma(p, r, 8.333333333333333e-03);
    p = fma(p, r, 4.166666666666666e-02);
    p = fma(p, r, 1.666666666666667e-01);
    p = fma(p, r, 0.5);
    p = fma(p, r, 1.0);
    p = fma(p, r, 1.0);
    long long ni = (long long)nf;
    double sc = __longlong_as_double((ni + 1023LL) << 52);
    return (float)(p * sc);
}

// ---------------- kernel 1: softmax + box decode (2 threads per row) ----------
__global__ void __launch_bounds__(64, 1)
softmax_decode_kernel(const float* __restrict__ locs,
                      const float* __restrict__ scores,
                      const float* __restrict__ priors)
{
    int gid  = blockIdx.x * blockDim.x + threadIdx.x;
    int row  = gid >> 1;
    int half = gid & 1;
    bool real = (row < NIMG * NPRI);
    if (!real) row = NIMG * NPRI - 1;          // clamp; keep lanes alive for shfl
    int img = row / NPRI;
    int p   = row - img * NPRI;

    const float* s  = scores + (size_t)row * NTOT;
    const float* l  = locs   + (size_t)row * 4;
    const float* pr = priors + (size_t)p * 4;

    // half0: classes 0..10 (11), half1: classes 11..20 (10)
    int c0 = half ? 11 : 0;
    int cn = half ? 10 : 11;

    float zv[11];
    float m = -INFINITY;
    #pragma unroll
    for (int k = 0; k < 11; k++) {
        if (k < cn) { zv[k] = s[c0 + k]; m = fmaxf(m, zv[k]); }
    }
    m = fmaxf(m, __shfl_xor_sync(0xffffffffu, m, 1));

    float e[11];
    double dsum = 0.0;
    #pragma unroll
    for (int k = 0; k < 11; k++) {
        if (k < cn) { e[k] = exp_df(zv[k] - m); dsum += (double)e[k]; }
    }
    // decode exp in parallel: half0 -> w, half1 -> h
    float dexp = half ? (exp_df(__fdiv_rn(l[3], 5.0f)) * pr[3])
                      : (exp_df(__fdiv_rn(l[2], 5.0f)) * pr[2]);

    dsum += __shfl_xor_sync(0xffffffffu, dsum, 1);
    float fsum = (float)dsum;

    if (real) {
        if (half == 0) {
            #pragma unroll
            for (int k = 1; k < 11; k++)          // skip background class 0
                g_cls[img][k - 1][p] = __fdiv_rn(e[k], fsum);
        } else {
            #pragma unroll
            for (int k = 0; k < 10; k++)
                g_cls[img][10 + k][p] = __fdiv_rn(e[k], fsum);
        }
    }

    float other = __shfl_xor_sync(0xffffffffu, dexp, 1);
    if (real && half == 0) {
        float w = dexp, h = other;
        float cx = __fdiv_rn(l[0] * pr[2], 10.0f) + pr[0];
        float cy = __fdiv_rn(l[1] * pr[3], 10.0f) + pr[1];
        float4 b;
        b.x = cx - __fdiv_rn(w, 2.0f);
        b.y = cy - __fdiv_rn(h, 2.0f);
        b.z = cx + __fdiv_rn(w, 2.0f);
        b.w = cy + __fdiv_rn(h, 2.0f);
        g_box[img][p] = b;
    }
}

// overlap test with precomputed areas; bit-identical to reference iou > T
__device__ __forceinline__ bool overlap_f(float4 a, float aA, float4 b, float aB)
{
    float dx = fminf(a.z, b.z) - fmaxf(a.x, b.x);
    float dy = fminf(a.w, b.w) - fmaxf(a.y, b.y);
    if (dx > 0.0f && dy > 0.0f) {
        float inter = dx * dy;
        return __fdiv_rn(inter, aA + aB - inter) > MAX_OVERLAP;
    }
    return false;   // inter==0 -> iou==0 <= T
}

// exclusive warp-count prefix via shfl scan; s_wcnt[lane] valid for lane<32.
__device__ __forceinline__ void scan_counts(const int* s_wcnt, int wid, int lane,
                                            int& wpre, int& wsum)
{
    int x = s_wcnt[lane];
    #pragma unroll
    for (int d = 1; d < 32; d <<= 1) {
        int v = __shfl_up_sync(0xffffffffu, x, d);
        if (lane >= d) x += v;
    }
    wsum = __shfl_sync(0xffffffffu, x, 31);
    wpre = (wid == 0) ? 0 : __shfl_sync(0xffffffffu, x, wid - 1);
}

// one register-resident bitonic micro-step on value v at element index e
__device__ __forceinline__ unsigned long long bitonic_reg_step(
    unsigned long long v, int e, int k, int j)
{
    unsigned long long pv = __shfl_xor_sync(0xffffffffu, v, j);
    bool down  = ((e & k) == 0);     // this region sorts descending
    bool lower = ((e & j) == 0);
    unsigned long long mx = (v > pv) ? v : pv;
    unsigned long long mn = (v > pv) ? pv : v;
    return (down == lower) ? mx : mn;
}

// ---------------- kernel 2: per-(image,class) greedy NMS ----------------
// Dynamic shared layout:
//   [0,      32768)   u64    skey64[NPAD]      (score_bits<<32 | ~idx)
//   [32768,  82464)   float4 sbox[NPRI]
//   [82464,  94888)   float  sscore[NPRI]
//   [94888, 107312)   float  sarea[NPRI]
#define SMEM_NMS_BYTES 107392

__global__ void __launch_bounds__(NMS_NT, 1)
nms_kernel()
{
    extern __shared__ char sm[];
    unsigned long long* skey64 = (unsigned long long*)(sm);
    float4*             sbox   = (float4*)(sm + 32768);
    float*              sscore = (float*)(sm + 82464);
    float*              sarea  = (float*)(sm + 94888);
    __shared__ int      s_wcnt[NWARPS];
    __shared__ unsigned s_row[CHUNK][2];
    __shared__ unsigned s_keptw[2];
    __shared__ int      s_klist[CHUNK];
    __shared__ int      s_nk;
    __shared__ float4   s_kbox[CHUNK];
    __shared__ float    s_karea[CHUNK];

    int img  = blockIdx.x / NCLS;
    int c    = blockIdx.x % NCLS;
    int tid  = threadIdx.x;
    int wid  = tid >> 5;
    int lane = tid & 31;
    unsigned lmask = (1u << lane) - 1u;

    // ---- Phase A: stable compaction of valid entries ----
    int base = 0;
    for (int bp = 0; bp < NPRI; bp += NMS_NT) {
        int p = bp + tid;
        float sc = (p < NPRI) ? g_cls[img][c][p] : 0.0f;
        bool ok = (p < NPRI) && (sc > MIN_SCORE);
        unsigned b = __ballot_sync(0xffffffffu, ok);
        if (lane == 0) s_wcnt[wid] = __popc(b);
        __syncthreads();
        int wpre, wsum;
        scan_counts(s_wcnt, wid, lane, wpre, wsum);
        int rank = base + wpre + __popc(b & lmask);
        if (ok)
            skey64[rank] = ((unsigned long long)__float_as_uint(sc) << 32)
                         | (unsigned int)(~p);
        base += wsum;
        __syncthreads();
    }
    int nvalid = base;

    int keptTotal = 0;

    if (nvalid > 0) {
        int npow = 32;
        while (npow < nvalid) npow <<= 1;
        for (int t = nvalid + tid; t < npow; t += NMS_NT)
            skey64[t] = 0ull;
        __syncthreads();

        // ---- Phase B: HYBRID bitonic sort (desc u64; score desc, idx asc) ----
        int nseg = (npow + NMS_NT - 1) / NMS_NT;

        // stages k = 2..32: entirely intra-warp (register + shfl)
        for (int q = 0; q < nseg; q++) {
            int e = q * NMS_NT + tid;
            if (e < npow) {               // whole warp uniform (npow % 32 == 0)
                unsigned long long v = skey64[e];
                #pragma unroll
                for (int k = 2; k <= 32; k <<= 1) {
                    #pragma unroll
                    for (int j = k >> 1; j >= 1; j >>= 1)
                        v = bitonic_reg_step(v, e, k, j);
                }
                skey64[e] = v;
            }
        }
        __syncthreads();

        // stages k = 64..npow: smem steps for j>=32, register tail j<=16
        for (int k = 64; k <= npow; k <<= 1) {
            for (int j = k >> 1; j >= 32; j >>= 1) {
                for (int t = tid; t < npow; t += NMS_NT) {
                    int l = t ^ j;
                    if (l > t) {
                        unsigned long long ka = skey64[t], kb = skey64[l];
                        bool asc = ((t & k) == 0);
                        if ((kb > ka) == asc) {
                            skey64[t] = kb;
                            skey64[l] = ka;
                        }
                    }
                }
                __syncthreads();
            }
            for (int q = 0; q < nseg; q++) {
                int e = q * NMS_NT + tid;
                if (e < npow) {
                    unsigned long long v = skey64[e];
                    #pragma unroll
                    for (int j = 16; j >= 1; j >>= 1)
                        v = bitonic_reg_step(v, e, k, j);
                    skey64[e] = v;
                }
            }
            __syncthreads();
        }

        // ---- Phase C: gather boxes + scores + areas ----
        for (int i = tid; i < nvalid; i += NMS_NT) {
            unsigned long long key = skey64[i];
            unsigned idx = ~((unsigned)key);
            float4 b = g_box[img][idx];
            sbox[i]   = b;
            sscore[i] = __uint_as_float((unsigned)(key >> 32));
            sarea[i]  = (b.z - b.x) * (b.w - b.y);
        }
        __syncthreads();

        // ---- Phase D: 64-wide chunked greedy (R11 form) ----
        int nrem = nvalid;
        while (nrem > 0 && keptTotal < TOPK) {
            int m = min(CHUNK, nrem);

            // 1) in-chunk upper-tri matrix rows via one-IoU-per-lane + ballot.
            if (wid < m) {
                int r = wid;
                float4 bi = sbox[r];
                float  ai = sarea[r];
                bool ov0 = (lane > r && lane < m)
                         ? overlap_f(bi, ai, sbox[lane], sarea[lane]) : false;
                int j2 = lane + 32;
                bool ov1 = (j2 < m)
                         ? overlap_f(bi, ai, sbox[j2], sarea[j2]) : false;
                unsigned w0 = __ballot_sync(0xffffffffu, ov0);
                unsigned w1 = __ballot_sync(0xffffffffu, ov1);
                if (lane == 0) { s_row[r][0] = w0; s_row[r][1] = w1; }
            }
            {
                int r2 = wid + 32;
                if (r2 < m) {
                    float4 bi = sbox[r2];
                    float  ai = sarea[r2];
                    int j2 = lane + 32;
                    bool ov = (j2 > r2 && j2 < m)
                            ? overlap_f(bi, ai, sbox[j2], sarea[j2]) : false;
                    unsigned w1 = __ballot_sync(0xffffffffu, ov);
                    if (lane == 0) { s_row[r2][0] = 0u; s_row[r2][1] = w1; }
                }
            }
            __syncthreads();

            // 2) serial resolve on one thread: pure bit ops, no IoU
            if (tid == 0) {
                unsigned sup0 = 0, sup1 = 0, k0 = 0, k1 = 0;
                int nk = 0;
                for (int i = 0; i < m; i++) {
                    bool s = (i < 32) ? ((sup0 >> i) & 1u)
                                      : ((sup1 >> (i - 32)) & 1u);
                    if (!s) {
                        if (i < 32) k0 |= 1u << i; else k1 |= 1u << (i - 32);
                        sup0 |= s_row[i][0];
                        sup1 |= s_row[i][1];
                        s_klist[nk++] = i;
                    }
                }
                s_keptw[0] = k0; s_keptw[1] = k1; s_nk = nk;
            }
            __syncthreads();

            int nk = s_nk;

            // 3) export kept + densify kept boxes (before compact overwrites!)
            if (tid < m) {
                int w = tid >> 5;
                unsigned km = s_keptw[w];
                if ((km >> lane) & 1u) {
                    int rank = ((w == 1) ? __popc(s_keptw[0]) : 0)
                             + __popc(km & lmask);
                    int slot = keptTotal + rank;
                    if (slot < TOPK) {
                        g_candScore[img][c][slot] = sscore[tid];
                        g_candBox[img][c][slot]   = sbox[tid];
                    }
                }
            }
            if (tid < nk) {
                int ki = s_klist[tid];
                s_kbox[tid]  = sbox[ki];
                s_karea[tid] = sarea[ki];
            }
            keptTotal += nk;
            if (keptTotal >= TOPK) break;
            if (nrem <= m) { nrem = 0; break; }
            __syncthreads();   // s_kbox ready; also guards sbox reads below

            // 4) fused suppress (vs nk kept, early-exit) + stable compact
            int newbase = 0;
            for (int start = m; start < nrem; start += NMS_NT) {
                int j = start + tid;
                bool ok = (j < nrem);
                float key = 0.0f, ar = 0.0f; float4 bx;
                if (ok) {
                    key = sscore[j]; bx = sbox[j]; ar = sarea[j];
                    for (int t = 0; t < nk; t++) {
                        if (overlap_f(s_kbox[t], s_karea[t], bx, ar)) {
                            ok = false; break;
                        }
                    }
                }
                unsigned b = __ballot_sync(0xffffffffu, ok);
                if (lane == 0) s_wcnt[wid] = __popc(b);
                __syncthreads();          // reads done; safe to write
                int wpre, wsum;
                scan_counts(s_wcnt, wid, lane, wpre, wsum);
                int rank = newbase + wpre + __popc(b & lmask);
                if (ok) { sscore[rank] = key; sbox[rank] = bx; sarea[rank] = ar; }
                newbase += wsum;
                __syncthreads();
            }
            nrem = newbase;
        }
    }

    // pad unused candidate slots; publish kept count
    int kc = min(keptTotal, TOPK);
    for (int r = kc + tid; r < TOPK; r += NMS_NT)
        g_candScore[img][c][r] = -INFINITY;
    if (tid == 0) g_candCnt[img][c] = keptTotal;
}

// ---------------- kernel 3: per-image rank-based parallel top-200 -------------
// Global rank of candidate (ca, ra) = ra + sum over other classes c2 of:
//   #{ j in c2 : key_j > ka }            if c2 > ca
//   #{ j in c2 : key_j >= ka }           if c2 < ca   (flat-index tie order)
// Per-class lists are sorted descending -> one binary search per class.
#define TKR_NT 1024
__global__ void __launch_bounds__(TKR_NT, 1)
topk_rank_kernel(float* __restrict__ out)
{
    __shared__ float ssc[NCLS * TOPK];
    __shared__ int   s_total;

    int img = blockIdx.x;
    int tid = threadIdx.x;

    const float* src = &g_candScore[img][0][0];
    for (int t = tid; t < NCLS * TOPK; t += TKR_NT)
        ssc[t] = src[t];
    if (tid == 0) {
        int tt = 0;
        for (int c = 0; c < NCLS; c++) tt += g_candCnt[img][c];
        s_total = tt;
    }
    __syncthreads();

    int found = min(s_total, TOPK);

    float* outBoxes  = out;                                     // [4,200,4]
    float* outLabels = out + NIMG * TOPK * 4;                   // [4,200]
    float* outScores = out + NIMG * TOPK * 4 + NIMG * TOPK;     // [4,200]
    float* outCount  = out + NIMG * TOPK * 4 + 2 * NIMG * TOPK; // [4]

    // defaults for slots [found, TOPK)
    for (int k = found + tid; k < TOPK; k += TKR_NT) {
        int basei = (img * TOPK + k) * 4;
        outBoxes[basei + 0] = 0.0f;
        outBoxes[basei + 1] = 0.0f;
        outBoxes[basei + 2] = 0.0f;
        outBoxes[basei + 3] = 0.0f;
        outLabels[img * TOPK + k] = 0.0f;
        outScores[img * TOPK + k] = 0.0f;
    }

    // rank computation (slots [0, found) get exactly one writer each)
    for (int e = tid; e < NCLS * TOPK; e += TKR_NT) {
        float ka = ssc[e];
        if (!(ka > -INFINITY)) continue;      // -inf padding
        int ca = e / TOPK;
        int ra = e - ca * TOPK;
        int rank = ra;
        for (int c2 = 0; c2 < NCLS && rank < TOPK; c2++) {
            if (c2 == ca) continue;
            const float* L = ssc + c2 * TOPK;
            int lo = 0, hi = TOPK;
            if (c2 < ca) {
                while (lo < hi) {             // count >= ka
                    int mid = (lo + hi) >> 1;
                    if (L[mid] >= ka) lo = mid + 1; else hi = mid;
                }
            } else {
                while (lo < hi) {             // count > ka
                    int mid = (lo + hi) >> 1;
                    if (L[mid] > ka) lo = mid + 1; else hi = mid;
                }
            }
            rank += lo;
        }
        if (rank < TOPK) {
            float4 b = g_candBox[img][ca][ra];
            int basei = (img * TOPK + rank) * 4;
            outBoxes[basei + 0] = b.x;
            outBoxes[basei + 1] = b.y;
            outBoxes[basei + 2] = b.z;
            outBoxes[basei + 3] = b.w;
            outLabels[img * TOPK + rank] = (float)(ca + 1);
            outScores[img * TOPK + rank] = ka;
        }
    }
    __syncthreads();

    if (tid == 0) {
        int cnt = found;
        if (cnt == 0) {
            int basei = img * TOPK * 4;
            outBoxes[basei + 0] = 0.0f;
            outBoxes[basei + 1] = 0.0f;
            outBoxes[basei + 2] = 1.0f;
            outBoxes[basei + 3] = 1.0f;
            cnt = 1;
        }
        outCount[img] = (float)cnt;
    }
}

// ---------------- launch ----------------
extern "C" void kernel_launch(void* const* d_in, const int* in_sizes, int n_in,
                              void* d_out, int out_size)
{
    const float* locs   = (const float*)d_in[0];  // (4,3106,4)
    const float* scores = (const float*)d_in[1];  // (4,3106,21)
    const float* priors = (const float*)d_in[2];  // (3106,4)
    float* out = (float*)d_out;

    static bool attr_set = false;
    if (!attr_set) {
        cudaFuncSetAttribute(nms_kernel,
                             cudaFuncAttributeMaxDynamicSharedMemorySize,
                             SMEM_NMS_BYTES);
        attr_set = true;
    }

    int threads2 = NIMG * NPRI * 2;               // 2 threads per row
    softmax_decode_kernel<<<(threads2 + 63) / 64, 64>>>(locs, scores, priors);
    nms_kernel<<<NIMG * NCLS, NMS_NT, SMEM_NMS_BYTES>>>();
    topk_rank_kernel<<<NIMG, TKR_NT>>>(out);
}

// round 14
// speedup vs baseline: 1.2719x; 1.1029x over previous
#include <cuda_runtime.h>
#include <math.h>
#include <limits.h>

#define NIMG 4
#define NPRI 3106
#define NCLS 20      // classes 1..20 (background excluded)
#define NTOT 21
#define NPAD 4096    // max pow2 bound for sort array
#define TOPK 200

#define MIN_SCORE 0.05f
#define MAX_OVERLAP 0.45f

#define NMS_NT 1024
#define NWARPS (NMS_NT / 32)   // 32

#define CHUNK 64

// ---------------- device scratch (no allocations allowed) ----------------
__device__ float  g_cls[NIMG][NCLS][NPRI];      // class-major probs
__device__ float4 g_box[NIMG][NPRI];            // decoded boxes x1,y1,x2,y2
__device__ float  g_candScore[NIMG][NCLS][TOPK];
__device__ float4 g_candBox[NIMG][NCLS][TOPK];
__device__ int    g_candCnt[NIMG][NCLS];

// Accurate fp32 exp via fp64 range-reduction + compensated (double-float)
// fp32 Horner. Relative error ~2^-45 -> fp32 result is the correctly-rounded
// exp for all but ~2^-20 of inputs (bit-identical to the previous fp64 path).
// All fp32 steps use explicit IEEE intrinsics -> immune to fast-math.
// Valid for |x| <= 85.
__device__ __forceinline__ float exp_ff(float x)
{
    float nf = rintf(x * 1.4426950408889634f);
    // r = x - nf*ln2, exactly split into fp32 head/tail via one fp64 fma
    double rd = fma((double)nf, -0.6931471805599453, (double)x);
    float rh = (float)rd;
    float rl = (float)(rd - (double)rh);

    // tail: degrees 12..7 in plain fp32 (contribution < 2^-21, error < 2^-45)
    float t;
    t = 2.0876756987868099e-9f;                    // 1/12!
    t = fmaf(t, rh, 2.5052108385441720e-8f);       // 1/11!
    t = fmaf(t, rh, 2.7557319223985893e-7f);       // 1/10!
    t = fmaf(t, rh, 2.7557319223985888e-6f);       // 1/9!
    t = fmaf(t, rh, 2.4801587301587302e-5f);       // 1/8!
    t = fmaf(t, rh, 1.9841269841269841e-4f);       // 1/7!

    // degrees 6..0 in double-float (TwoProdFMA + quick-two-sum)
    const float C[7] = { 1.3888888888888889e-3f,   // 1/6!
                         8.3333333333333332e-3f,   // 1/5!
                         4.1666666666666664e-2f,   // 1/4!
                         1.6666666666666666e-1f,   // 1/3!
                         0.5f, 1.0f, 1.0f };
    float ah = t, al = 0.0f;
    #pragma unroll
    for (int k = 0; k < 7; k++) {
        float ph = __fmul_rn(ah, rh);
        float pl = fmaf(ah, rh, -ph);              // exact product residual
        pl = fmaf(al, rh, pl);
        float ck = C[k];
        float sh = __fadd_rn(ck, ph);              // |ck| >= |ph| holds here
        float sl = __fsub_rn(ph, __fsub_rn(sh, ck));
        al = __fadd_rn(pl, sl);
        ah = sh;
    }
    // fold in rl: exp(rh+rl) ~= exp(rh)*(1+rl)
    float res = __fadd_rn(fmaf(ah, rl, al), ah);
    // scale by 2^n (exact; n in [-126, 127] for our inputs)
    return res * __int_as_float(((int)nf + 127) << 23);
}

// ---------------- kernel 1: softmax + box decode (thread per row) ----------
__global__ void __launch_bounds__(64, 1)
softmax_decode_kernel(const float* __restrict__ locs,
                      const float* __restrict__ scores,
                      const float* __restrict__ priors)
{
    int row = blockIdx.x * blockDim.x + threadIdx.x;
    if (row >= NIMG * NPRI) return;
    int img = row / NPRI;
    int p   = row - img * NPRI;

    const float* s = scores + (size_t)row * NTOT;
    float m = s[0];
    #pragma unroll
    for (int c = 1; c < NTOT; c++) m = fmaxf(m, s[c]);

    float e[NTOT];
    double dsum = 0.0;
    #pragma unroll
    for (int c = 0; c < NTOT; c++) {
        e[c] = exp_ff(s[c] - m);
        dsum += (double)e[c];
    }
    float fsum = (float)dsum;
    #pragma unroll
    for (int c = 1; c < NTOT; c++)
        g_cls[img][c - 1][p] = __fdiv_rn(e[c], fsum);

    const float* l  = locs + (size_t)row * 4;
    const float* pr = priors + (size_t)p * 4;
    float cx = __fdiv_rn(l[0] * pr[2], 10.0f) + pr[0];
    float cy = __fdiv_rn(l[1] * pr[3], 10.0f) + pr[1];
    float w  = exp_ff(__fdiv_rn(l[2], 5.0f)) * pr[2];
    float h  = exp_ff(__fdiv_rn(l[3], 5.0f)) * pr[3];
    float4 b;
    b.x = cx - __fdiv_rn(w, 2.0f);
    b.y = cy - __fdiv_rn(h, 2.0f);
    b.z = cx + __fdiv_rn(w, 2.0f);
    b.w = cy + __fdiv_rn(h, 2.0f);
    g_box[img][p] = b;
}

// overlap test with precomputed areas; bit-identical to reference iou > T
__device__ __forceinline__ bool overlap_f(float4 a, float aA, float4 b, float aB)
{
    float dx = fminf(a.z, b.z) - fmaxf(a.x, b.x);
    float dy = fminf(a.w, b.w) - fmaxf(a.y, b.y);
    if (dx > 0.0f && dy > 0.0f) {
        float inter = dx * dy;
        return __fdiv_rn(inter, aA + aB - inter) > MAX_OVERLAP;
    }
    return false;   // inter==0 -> iou==0 <= T
}

// exclusive warp-count prefix via shfl scan; s_wcnt[lane] valid for lane<32.
__device__ __forceinline__ void scan_counts(const int* s_wcnt, int wid, int lane,
                                            int& wpre, int& wsum)
{
    int x = s_wcnt[lane];
    #pragma unroll
    for (int d = 1; d < 32; d <<= 1) {
        int v = __shfl_up_sync(0xffffffffu, x, d);
        if (lane >= d) x += v;
    }
    wsum = __shfl_sync(0xffffffffu, x, 31);
    wpre = (wid == 0) ? 0 : __shfl_sync(0xffffffffu, x, wid - 1);
}

// one register-resident bitonic micro-step on value v at element index e
__device__ __forceinline__ unsigned long long bitonic_reg_step(
    unsigned long long v, int e, int k, int j)
{
    unsigned long long pv = __shfl_xor_sync(0xffffffffu, v, j);
    bool down  = ((e & k) == 0);     // this region sorts descending
    bool lower = ((e & j) == 0);
    unsigned long long mx = (v > pv) ? v : pv;
    unsigned long long mn = (v > pv) ? pv : v;
    return (down == lower) ? mx : mn;
}

// ---------------- kernel 2: per-(image,class) greedy NMS ----------------
// Dynamic shared layout:
//   [0,      32768)   u64    skey64[NPAD]      (score_bits<<32 | ~idx)
//   [32768,  82464)   float4 sbox[NPRI]
//   [82464,  94888)   float  sscore[NPRI]
//   [94888, 107312)   float  sarea[NPRI]
#define SMEM_NMS_BYTES 107392

__global__ void __launch_bounds__(NMS_NT, 1)
nms_kernel()
{
    extern __shared__ char sm[];
    unsigned long long* skey64 = (unsigned long long*)(sm);
    float4*             sbox   = (float4*)(sm + 32768);
    float*              sscore = (float*)(sm + 82464);
    float*              sarea  = (float*)(sm + 94888);
    __shared__ int      s_wcnt[NWARPS];
    __shared__ unsigned s_row[CHUNK][2];
    __shared__ unsigned s_keptw[2];
    __shared__ int      s_nk;
    __shared__ float4   s_kbox[CHUNK];
    __shared__ float    s_karea[CHUNK];

    int img  = blockIdx.x / NCLS;
    int c    = blockIdx.x % NCLS;
    int tid  = threadIdx.x;
    int wid  = tid >> 5;
    int lane = tid & 31;
    unsigned lmask = (1u << lane) - 1u;

    // ---- Phase A: stable compaction of valid entries ----
    int base = 0;
    for (int bp = 0; bp < NPRI; bp += NMS_NT) {
        int p = bp + tid;
        float sc = (p < NPRI) ? g_cls[img][c][p] : 0.0f;
        bool ok = (p < NPRI) && (sc > MIN_SCORE);
        unsigned b = __ballot_sync(0xffffffffu, ok);
        if (lane == 0) s_wcnt[wid] = __popc(b);
        __syncthreads();
        int wpre, wsum;
        scan_counts(s_wcnt, wid, lane, wpre, wsum);
        int rank = base + wpre + __popc(b & lmask);
        if (ok)
            skey64[rank] = ((unsigned long long)__float_as_uint(sc) << 32)
                         | (unsigned int)(~p);
        base += wsum;
        __syncthreads();
    }
    int nvalid = base;

    int keptTotal = 0;

    if (nvalid > 0) {
        int npow = 32;
        while (npow < nvalid) npow <<= 1;
        for (int t = nvalid + tid; t < npow; t += NMS_NT)
            skey64[t] = 0ull;
        __syncthreads();

        // ---- Phase B: HYBRID bitonic sort (desc u64; score desc, idx asc) ----
        int nseg = (npow + NMS_NT - 1) / NMS_NT;

        // stages k = 2..32: entirely intra-warp (register + shfl)
        for (int q = 0; q < nseg; q++) {
            int e = q * NMS_NT + tid;
            if (e < npow) {               // whole warp uniform (npow % 32 == 0)
                unsigned long long v = skey64[e];
                #pragma unroll
                for (int k = 2; k <= 32; k <<= 1) {
                    #pragma unroll
                    for (int j = k >> 1; j >= 1; j >>= 1)
                        v = bitonic_reg_step(v, e, k, j);
                }
                skey64[e] = v;
            }
        }
        __syncthreads();

        // stages k = 64..npow: smem steps for j>=32, register tail j<=16
        for (int k = 64; k <= npow; k <<= 1) {
            for (int j = k >> 1; j >= 32; j >>= 1) {
                for (int t = tid; t < npow; t += NMS_NT) {
                    int l = t ^ j;
                    if (l > t) {
                        unsigned long long ka = skey64[t], kb = skey64[l];
                        bool asc = ((t & k) == 0);
                        if ((kb > ka) == asc) {
                            skey64[t] = kb;
                            skey64[l] = ka;
                        }
                    }
                }
                __syncthreads();
            }
            for (int q = 0; q < nseg; q++) {
                int e = q * NMS_NT + tid;
                if (e < npow) {
                    unsigned long long v = skey64[e];
                    #pragma unroll
                    for (int j = 16; j >= 1; j >>= 1)
                        v = bitonic_reg_step(v, e, k, j);
                    skey64[e] = v;
                }
            }
            __syncthreads();
        }

        // ---- Phase C: gather boxes + scores + areas ----
        for (int i = tid; i < nvalid; i += NMS_NT) {
            unsigned long long key = skey64[i];
            unsigned idx = ~((unsigned)key);
            float4 b = g_box[img][idx];
            sbox[i]   = b;
            sscore[i] = __uint_as_float((unsigned)(key >> 32));
            sarea[i]  = (b.z - b.x) * (b.w - b.y);
        }
        __syncthreads();

        // ---- Phase D: 64-wide chunked greedy ----
        int nrem = nvalid;
        while (nrem > 0 && keptTotal < TOPK) {
            int m = min(CHUNK, nrem);

            // 1) in-chunk upper-tri matrix rows via one-IoU-per-lane + ballot.
            if (wid < m) {
                int r = wid;
                float4 bi = sbox[r];
                float  ai = sarea[r];
                bool ov0 = (lane > r && lane < m)
                         ? overlap_f(bi, ai, sbox[lane], sarea[lane]) : false;
                int j2 = lane + 32;
                bool ov1 = (j2 < m)
                         ? overlap_f(bi, ai, sbox[j2], sarea[j2]) : false;
                unsigned w0 = __ballot_sync(0xffffffffu, ov0);
                unsigned w1 = __ballot_sync(0xffffffffu, ov1);
                if (lane == 0) { s_row[r][0] = w0; s_row[r][1] = w1; }
            }
            {
                int r2 = wid + 32;
                if (r2 < m) {
                    float4 bi = sbox[r2];
                    float  ai = sarea[r2];
                    int j2 = lane + 32;
                    bool ov = (j2 > r2 && j2 < m)
                            ? overlap_f(bi, ai, sbox[j2], sarea[j2]) : false;
                    unsigned w1 = __ballot_sync(0xffffffffu, ov);
                    if (lane == 0) { s_row[r2][0] = 0u; s_row[r2][1] = w1; }
                }
            }
            __syncthreads();

            // 2) warp 0: ballot resolve with lane-held row masks (no IoU,
            //    iterations = number of kept boxes only)
            if (wid == 0) {
                unsigned r0w0 = 0u, r0w1 = 0u, r1w1 = 0u;
                if (lane < m)      { r0w0 = s_row[lane][0]; r0w1 = s_row[lane][1]; }
                if (lane + 32 < m)   r1w1 = s_row[lane + 32][1];
                unsigned valid0 = (m >= 32) ? 0xffffffffu : ((1u << m) - 1u);
                unsigned valid1 = (m > 32)
                                ? ((m >= 64) ? 0xffffffffu : ((1u << (m - 32)) - 1u))
                                : 0u;
                unsigned sup1 = 0u, kept0 = 0u, kept1 = 0u;
                unsigned unres = valid0;
                while (unres) {
                    int i = __ffs(unres) - 1;
                    kept0 |= 1u << i;
                    unsigned ri0 = __shfl_sync(0xffffffffu, r0w0, i);
                    unsigned ri1 = __shfl_sync(0xffffffffu, r0w1, i);
                    sup1 |= ri1;
                    unres &= ~(ri0 | (1u << i));
                }
                unres = valid1 & ~sup1;
                while (unres) {
                    int i = __ffs(unres) - 1;
                    kept1 |= 1u << i;
                    unsigned ri1 = __shfl_sync(0xffffffffu, r1w1, i);
                    unres &= ~(ri1 | (1u << i));
                }
                if (lane == 0) {
                    s_keptw[0] = kept0;
                    s_keptw[1] = kept1;
                    s_nk = __popc(kept0) + __popc(kept1);
                }
            }
            __syncthreads();

            int nk = s_nk;

            // 3) export kept + densify kept boxes via keptw ranks
            if (tid < m) {
                int w = tid >> 5;
                unsigned km = s_keptw[w];
                if ((km >> lane) & 1u) {
                    int rank = ((w == 1) ? __popc(s_keptw[0]) : 0)
                             + __popc(km & lmask);
                    int slot = keptTotal + rank;
                    if (slot < TOPK) {
                        g_candScore[img][c][slot] = sscore[tid];
                        g_candBox[img][c][slot]   = sbox[tid];
                    }
                    s_kbox[rank]  = sbox[tid];
                    s_karea[rank] = sarea[tid];
                }
            }
            keptTotal += nk;
            if (keptTotal >= TOPK) break;
            if (nrem <= m) { nrem = 0; break; }
            __syncthreads();   // s_kbox ready; also guards sbox reads below

            // 4) fused suppress (vs nk kept, early-exit) + stable compact
            int newbase = 0;
            for (int start = m; start < nrem; start += NMS_NT) {
                int j = start + tid;
                bool ok = (j < nrem);
                float key = 0.0f, ar = 0.0f; float4 bx;
                if (ok) {
                    key = sscore[j]; bx = sbox[j]; ar = sarea[j];
                    for (int t = 0; t < nk; t++) {
                        if (overlap_f(s_kbox[t], s_karea[t], bx, ar)) {
                            ok = false; break;
                        }
                    }
                }
                unsigned b = __ballot_sync(0xffffffffu, ok);
                if (lane == 0) s_wcnt[wid] = __popc(b);
                __syncthreads();          // reads done; safe to write
                int wpre, wsum;
                scan_counts(s_wcnt, wid, lane, wpre, wsum);
                int rank = newbase + wpre + __popc(b & lmask);
                if (ok) { sscore[rank] = key; sbox[rank] = bx; sarea[rank] = ar; }
                newbase += wsum;
                __syncthreads();
            }
            nrem = newbase;
        }
    }

    // pad unused candidate slots; publish kept count
    int kc = min(keptTotal, TOPK);
    for (int r = kc + tid; r < TOPK; r += NMS_NT)
        g_candScore[img][c][r] = -INFINITY;
    if (tid == 0) g_candCnt[img][c] = keptTotal;
}

// ---------------- kernel 3: per-image rank-based parallel top-200 -------------
#define TKR_NT 1024
__global__ void __launch_bounds__(TKR_NT, 1)
topk_rank_kernel(float* __restrict__ out)
{
    __shared__ float ssc[NCLS * TOPK];
    __shared__ int   s_total;

    int img = blockIdx.x;
    int tid = threadIdx.x;

    const float* src = &g_candScore[img][0][0];
    for (int t = tid; t < NCLS * TOPK; t += TKR_NT)
        ssc[t] = src[t];
    if (tid == 0) {
        int tt = 0;
        for (int c = 0; c < NCLS; c++) tt += g_candCnt[img][c];
        s_total = tt;
    }
    __syncthreads();

    int found = min(s_total, TOPK);

    float* outBoxes  = out;                                     // [4,200,4]
    float* outLabels = out + NIMG * TOPK * 4;                   // [4,200]
    float* outScores = out + NIMG * TOPK * 4 + NIMG * TOPK;     // [4,200]
    float* outCount  = out + NIMG * TOPK * 4 + 2 * NIMG * TOPK; // [4]

    // defaults for slots [found, TOPK)
    for (int k = found + tid; k < TOPK; k += TKR_NT) {
        int basei = (img * TOPK + k) * 4;
        outBoxes[basei + 0] = 0.0f;
        outBoxes[basei + 1] = 0.0f;
        outBoxes[basei + 2] = 0.0f;
        outBoxes[basei + 3] = 0.0f;
        outLabels[img * TOPK + k] = 0.0f;
        outScores[img * TOPK + k] = 0.0f;
    }

    // rank computation (slots [0, found) get exactly one writer each)
    for (int e = tid; e < NCLS * TOPK; e += TKR_NT) {
        float ka = ssc[e];
        if (!(ka > -INFINITY)) continue;      // -inf padding
        int ca = e / TOPK;
        int ra = e - ca * TOPK;
        int rank = ra;
        for (int c2 = 0; c2 < NCLS && rank < TOPK; c2++) {
            if (c2 == ca) continue;
            const float* L = ssc + c2 * TOPK;
            int lo = 0, hi = TOPK;
            if (c2 < ca) {
                while (lo < hi) {             // count >= ka
                    int mid = (lo + hi) >> 1;
                    if (L[mid] >= ka) lo = mid + 1; else hi = mid;
                }
            } else {
                while (lo < hi) {             // count > ka
                    int mid = (lo + hi) >> 1;
                    if (L[mid] > ka) lo = mid + 1; else hi = mid;
                }
            }
            rank += lo;
        }
        if (rank < TOPK) {
            float4 b = g_candBox[img][ca][ra];
            int basei = (img * TOPK + rank) * 4;
            outBoxes[basei + 0] = b.x;
            outBoxes[basei + 1] = b.y;
            outBoxes[basei + 2] = b.z;
            outBoxes[basei + 3] = b.w;
            outLabels[img * TOPK + rank] = (float)(ca + 1);
            outScores[img * TOPK + rank] = ka;
        }
    }
    __syncthreads();

    if (tid == 0) {
        int cnt = found;
        if (cnt == 0) {
            int basei = img * TOPK * 4;
            outBoxes[basei + 0] = 0.0f;
            outBoxes[basei + 1] = 0.0f;
            outBoxes[basei + 2] = 1.0f;
            outBoxes[basei + 3] = 1.0f;
            cnt = 1;
        }
        outCount[img] = (float)cnt;
    }
}

// ---------------- launch ----------------
extern "C" void kernel_launch(void* const* d_in, const int* in_sizes, int n_in,
                              void* d_out, int out_size)
{
    const float* locs   = (const float*)d_in[0];  // (4,3106,4)
    const float* scores = (const float*)d_in[1];  // (4,3106,21)
    const float* priors = (const float*)d_in[2];  // (3106,4)
    float* out = (float*)d_out;

    static bool attr_set = false;
    if (!attr_set) {
        cudaFuncSetAttribute(nms_kernel,
                             cudaFuncAttributeMaxDynamicSharedMemorySize,
                             SMEM_NMS_BYTES);
        attr_set = true;
    }

    int rows = NIMG * NPRI;
    softmax_decode_kernel<<<(rows + 63) / 64, 64>>>(locs, scores, priors);
    nms_kernel<<<NIMG * NCLS, NMS_NT, SMEM_NMS_BYTES>>>();
    topk_rank_kernel<<<NIMG, TKR_NT>>>(out);
}